// round 10
// baseline (speedup 1.0000x reference)
#include <cuda_runtime.h>
#include <cuda_fp16.h>
#include <math.h>

#define N_NODES  100000
#define N_EDGES  3200000
#define N_GRAPHS 512
#define F_IN     128
#define F_HID    64
#define F_OUT    10

#define SCAN_B   512
#define NBLK     ((N_NODES + SCAN_B - 1) / SCAN_B)   // 196

#define GEMM_TPB    128
#define GEMM_NODES  16
#define GEMM_GRID   1184

// ---------------- scratch (device globals: no allocation allowed) ----------
__device__ int         g_count [N_NODES];
__device__ int         g_cursor[N_NODES];
__device__ int         g_off   [N_NODES + 1];
__device__ int         g_bsum  [NBLK];
__device__ int         g_boff  [NBLK];
__device__ int         g_src   [N_EDGES];
__device__ float       g_dinv  [N_NODES];
__device__ signed char g_q     [N_NODES * 64];   // int8 messages (64B/row)
__device__ float       g_mscale[N_NODES];        // per-row dequant scale
__device__ __half2     g_xh1   [N_NODES * 32];   // activations, fp16
__device__ __half2     g_xh2   [N_NODES * 32];
__device__ __half2     g_xh3   [N_NODES * 32];
__device__ int         g_start [N_GRAPHS + 1];
__device__ float       g_pool  [N_GRAPHS * 3 * F_HID];

// ---------------- packed f32x2 helpers --------------------------------------
__device__ __forceinline__ void ffma2(unsigned long long& acc, float x,
                                      unsigned long long w) {
    unsigned long long xx;
    asm("mov.b64 %0, {%1, %1};" : "=l"(xx) : "f"(x));
    asm("fma.rn.f32x2 %0, %1, %2, %0;" : "+l"(acc) : "l"(xx), "l"(w));
}
__device__ __forceinline__ float2 unpack2(unsigned long long v) {
    float2 r;
    asm("mov.b64 {%0, %1}, %2;" : "=f"(r.x), "=f"(r.y) : "l"(v));
    return r;
}
__device__ __forceinline__ float warp_max(float m) {
    for (int o = 16; o; o >>= 1)
        m = fmaxf(m, __shfl_xor_sync(0xffffffff, m, o));
    return m;
}

// ---------------- prep (unchanged from R9) -----------------------------------
__global__ void init_kernel() {
    int i = blockIdx.x * blockDim.x + threadIdx.x;
    int stride = gridDim.x * blockDim.x;
    for (int k = i; k < N_NODES; k += stride) { g_count[k] = 0; g_cursor[k] = 0; }
    for (int k = i; k <= N_GRAPHS; k += stride) g_start[k] = -1;
}

__global__ void count_kernel(const int* __restrict__ ei) {
    int e = blockIdx.x * blockDim.x + threadIdx.x;
    if (e >= N_EDGES) return;
    unsigned c = (unsigned)ei[N_EDGES + e];
    if (c < N_NODES) atomicAdd(&g_count[c], 1);
}

__global__ void scan1_kernel() {
    __shared__ int s[SCAN_B];
    int t = threadIdx.x;
    int i = blockIdx.x * SCAN_B + t;
    int v = (i < N_NODES) ? g_count[i] : 0;
    if (i < N_NODES) g_dinv[i] = (v > 0) ? rsqrtf((float)v) : 0.0f;
    s[t] = v; __syncthreads();
    int x = v;
    for (int o = 1; o < SCAN_B; o <<= 1) {
        int y = (t >= o) ? s[t - o] : 0;
        __syncthreads();
        x += y; s[t] = x;
        __syncthreads();
    }
    if (i < N_NODES) g_off[i] = x - v;
    if (t == SCAN_B - 1) g_bsum[blockIdx.x] = x;
}

__global__ void scan2_kernel() {
    __shared__ int s[256];
    int t = threadIdx.x;
    int v = (t < NBLK) ? g_bsum[t] : 0;
    s[t] = v; __syncthreads();
    int x = v;
    for (int o = 1; o < 256; o <<= 1) {
        int y = (t >= o) ? s[t - o] : 0;
        __syncthreads();
        x += y; s[t] = x;
        __syncthreads();
    }
    if (t < NBLK) g_boff[t] = x - v;
}

__global__ void scan3_kernel() {
    int i = blockIdx.x * blockDim.x + threadIdx.x;
    if (i < N_NODES) g_off[i] += g_boff[i / SCAN_B];
    if (i == 0) g_off[N_NODES] = N_EDGES;
}

__global__ void scatter_kernel(const int* __restrict__ ei) {
    int e = blockIdx.x * blockDim.x + threadIdx.x;
    if (e >= N_EDGES) return;
    int r = ei[e];
    unsigned c = (unsigned)ei[N_EDGES + e];
    if (c >= N_NODES) return;
    int pos = g_off[c] + atomicAdd(&g_cursor[c], 1);
    g_src[pos] = r;
}

// ------- GEMM: q[n] = int8( (X[n,:K] @ W) * dinv[n] / scale[n] ) ------------
template <int K>
__global__ __launch_bounds__(GEMM_TPB) void gemm_kernel(
        const float* __restrict__ Xext, const float* __restrict__ W, int src) {
    constexpr int K2 = K / 2;
    __shared__ ulonglong2 sW[K2 * 32];
    __shared__ float2     sX[GEMM_NODES * K2];

    const unsigned long long* Wu = (const unsigned long long*)W;
    for (int i = threadIdx.x; i < K2 * 32; i += GEMM_TPB) {
        int k2 = i >> 5, l = i & 31;
        sW[i] = make_ulonglong2(Wu[(2 * k2) * 32 + l], Wu[(2 * k2 + 1) * 32 + l]);
    }

    const __half2* Xh = (src == 1) ? g_xh1 : g_xh2;
    int warp = threadIdx.x >> 5;
    int lane = threadIdx.x & 31;

    const int NTILES = N_NODES / GEMM_NODES;
    for (int tile = blockIdx.x; tile < NTILES; tile += gridDim.x) {
        int node0 = tile * GEMM_NODES;
        __syncthreads();
        if (src == 0) {
            const float4* s = (const float4*)(Xext + (size_t)node0 * K);
            float4* d = (float4*)sX;
            for (int i = threadIdx.x; i < GEMM_NODES * K / 4; i += GEMM_TPB)
                d[i] = s[i];
        } else {
            const __half2* s = Xh + (size_t)node0 * 32;
            for (int i = threadIdx.x; i < GEMM_NODES * 32; i += GEMM_TPB)
                sX[i] = __half22float2(s[i]);
        }
        __syncthreads();

        int nb = warp * 4;
        unsigned long long a0 = 0, a1 = 0, a2 = 0, a3 = 0;
        const float2* x0p = &sX[(nb + 0) * K2];
        const float2* x1p = &sX[(nb + 1) * K2];
        const float2* x2p = &sX[(nb + 2) * K2];
        const float2* x3p = &sX[(nb + 3) * K2];
#pragma unroll 8
        for (int k2 = 0; k2 < K2; k2++) {
            ulonglong2 w = sW[k2 * 32 + lane];
            float2 x0 = x0p[k2], x1 = x1p[k2], x2 = x2p[k2], x3 = x3p[k2];
            ffma2(a0, x0.x, w.x); ffma2(a0, x0.y, w.y);
            ffma2(a1, x1.x, w.x); ffma2(a1, x1.y, w.y);
            ffma2(a2, x2.x, w.x); ffma2(a2, x2.y, w.y);
            ffma2(a3, x3.x, w.x); ffma2(a3, x3.y, w.y);
        }
        int n = node0 + nb;
        float2 f0 = unpack2(a0), f1 = unpack2(a1);
        float2 f2 = unpack2(a2), f3 = unpack2(a3);
        float d0 = g_dinv[n + 0], d1 = g_dinv[n + 1];
        float d2 = g_dinv[n + 2], d3 = g_dinv[n + 3];
        f0.x *= d0; f0.y *= d0;  f1.x *= d1; f1.y *= d1;
        f2.x *= d2; f2.y *= d2;  f3.x *= d3; f3.y *= d3;

        // per-row max -> int8 quantization
        float m0 = warp_max(fmaxf(fabsf(f0.x), fabsf(f0.y)));
        float m1 = warp_max(fmaxf(fabsf(f1.x), fabsf(f1.y)));
        float m2 = warp_max(fmaxf(fabsf(f2.x), fabsf(f2.y)));
        float m3 = warp_max(fmaxf(fabsf(f3.x), fabsf(f3.y)));
        float i0 = (m0 > 0.f) ? 127.0f / m0 : 0.f;
        float i1 = (m1 > 0.f) ? 127.0f / m1 : 0.f;
        float i2 = (m2 > 0.f) ? 127.0f / m2 : 0.f;
        float i3 = (m3 > 0.f) ? 127.0f / m3 : 0.f;
        char2* Q = (char2*)g_q;
        char2 q;
        q.x = (signed char)__float2int_rn(f0.x * i0);
        q.y = (signed char)__float2int_rn(f0.y * i0);
        Q[(n + 0) * 32 + lane] = q;
        q.x = (signed char)__float2int_rn(f1.x * i1);
        q.y = (signed char)__float2int_rn(f1.y * i1);
        Q[(n + 1) * 32 + lane] = q;
        q.x = (signed char)__float2int_rn(f2.x * i2);
        q.y = (signed char)__float2int_rn(f2.y * i2);
        Q[(n + 2) * 32 + lane] = q;
        q.x = (signed char)__float2int_rn(f3.x * i3);
        q.y = (signed char)__float2int_rn(f3.y * i3);
        Q[(n + 3) * 32 + lane] = q;
        if (lane == 0) {
            const float r = 1.0f / 127.0f;
            ((float4*)g_mscale)[n >> 2] =
                make_float4(m0 * r, m1 * r, m2 * r, m3 * r);
        }
    }
}

// ------- aggregate: int8 gather + dequant + bias + relu ---------------------
// 1 warp/node; lane = (half, fl): fl covers features 4fl..4fl+3 via one char4
// load (64B row / 16 lanes); halves process even/odd edges; shfl combine.
__device__ __forceinline__ void deq4(float& ax, float& ay, float& az, float& aw,
                                     char4 c, float s) {
    ax = fmaf((float)c.x, s, ax);
    ay = fmaf((float)c.y, s, ay);
    az = fmaf((float)c.z, s, az);
    aw = fmaf((float)c.w, s, aw);
}

__global__ void aggregate_kernel(const float* __restrict__ b, int dst) {
    int node = blockIdx.x * 8 + (threadIdx.x >> 5);
    int lane = threadIdx.x & 31;
    if (node >= N_NODES) return;
    int half = lane >> 4;
    int fl   = lane & 15;

    const char4* Q = (const char4*)g_q;   // row = 16 char4 = 64B
    int beg = g_off[node], end = g_off[node + 1];
    float ax = 0.f, ay = 0.f, az = 0.f, aw = 0.f;

    int e = beg;
    for (; e < end && (e & 3); e++) {
        if (half == 0) {
            int s = __ldg(&g_src[e]);
            deq4(ax, ay, az, aw, __ldg(&Q[s * 16 + fl]), __ldg(&g_mscale[s]));
        }
    }
    const int4* s4 = (const int4*)g_src;
    for (; e + 8 <= end; e += 8) {
        int4 i0 = __ldg(&s4[e >> 2]);
        int4 i1 = __ldg(&s4[(e >> 2) + 1]);
        int sA = half ? i0.y : i0.x;
        int sB = half ? i0.w : i0.z;
        int sC = half ? i1.y : i1.x;
        int sD = half ? i1.w : i1.z;
        char4 vA = __ldg(&Q[sA * 16 + fl]);
        char4 vB = __ldg(&Q[sB * 16 + fl]);
        char4 vC = __ldg(&Q[sC * 16 + fl]);
        char4 vD = __ldg(&Q[sD * 16 + fl]);
        float cA = __ldg(&g_mscale[sA]);
        float cB = __ldg(&g_mscale[sB]);
        float cC = __ldg(&g_mscale[sC]);
        float cD = __ldg(&g_mscale[sD]);
        deq4(ax, ay, az, aw, vA, cA);
        deq4(ax, ay, az, aw, vB, cB);
        deq4(ax, ay, az, aw, vC, cC);
        deq4(ax, ay, az, aw, vD, cD);
    }
    if (e + 4 <= end) {
        int4 i0 = __ldg(&s4[e >> 2]);
        int sA = half ? i0.y : i0.x;
        int sB = half ? i0.w : i0.z;
        char4 vA = __ldg(&Q[sA * 16 + fl]);
        char4 vB = __ldg(&Q[sB * 16 + fl]);
        float cA = __ldg(&g_mscale[sA]);
        float cB = __ldg(&g_mscale[sB]);
        deq4(ax, ay, az, aw, vA, cA);
        deq4(ax, ay, az, aw, vB, cB);
        e += 4;
    }
    for (; e < end; e++) {
        if (half == 0) {
            int s = __ldg(&g_src[e]);
            deq4(ax, ay, az, aw, __ldg(&Q[s * 16 + fl]), __ldg(&g_mscale[s]));
        }
    }

    ax += __shfl_xor_sync(0xffffffff, ax, 16);
    ay += __shfl_xor_sync(0xffffffff, ay, 16);
    az += __shfl_xor_sync(0xffffffff, az, 16);
    aw += __shfl_xor_sync(0xffffffff, aw, 16);

    if (half == 0) {
        float di = g_dinv[node];
        float4 bb = __ldg(&((const float4*)b)[fl]);
        float vx = fmaxf(fmaf(ax, di, bb.x), 0.0f);
        float vy = fmaxf(fmaf(ay, di, bb.y), 0.0f);
        float vz = fmaxf(fmaf(az, di, bb.z), 0.0f);
        float vw = fmaxf(fmaf(aw, di, bb.w), 0.0f);
        __half2 h0 = __floats2half2_rn(vx, vy);
        __half2 h1 = __floats2half2_rn(vz, vw);
        float2 st;
        *(__half2*)&st.x = h0;
        *(__half2*)&st.y = h1;
        float2* out = (float2*)((dst == 1) ? g_xh1 : (dst == 2) ? g_xh2 : g_xh3);
        out[node * 16 + fl] = st;
    }
}

// ---------------- pooling over sorted batch (unchanged) ----------------------
__global__ void start_set_kernel(const int* __restrict__ batch) {
    int i = blockIdx.x * blockDim.x + threadIdx.x;
    if (i >= N_NODES) return;
    int bcur = batch[i];
    if ((unsigned)bcur >= N_GRAPHS) return;
    if (i == 0 || batch[i - 1] != bcur) g_start[bcur] = i;
    if (i == 0) g_start[N_GRAPHS] = N_NODES;
}

__global__ void start_fix_kernel() {
    __shared__ int s[N_GRAPHS + 1];
    int t = threadIdx.x;
    for (int k = t; k <= N_GRAPHS; k += blockDim.x) s[k] = g_start[k];
    __syncthreads();
    if (t == 0) {
        int nxt = s[N_GRAPHS];
        for (int g = N_GRAPHS - 1; g >= 0; --g) {
            if (s[g] < 0) s[g] = nxt;
            nxt = s[g];
        }
    }
    __syncthreads();
    for (int k = t; k <= N_GRAPHS; k += blockDim.x) g_start[k] = s[k];
}

__global__ void pool_kernel() {
    int g = blockIdx.x;
    int t = threadIdx.x;                  // 0..95
    int layer = t >> 5, p = t & 31;
    int beg = g_start[g], end = g_start[g + 1];
    const __half2* src = (layer == 0) ? g_xh1 : (layer == 1) ? g_xh2 : g_xh3;
    float x0 = 0.f, y0 = 0.f, x1 = 0.f, y1 = 0.f;
    float x2 = 0.f, y2 = 0.f, x3 = 0.f, y3 = 0.f;
    int n = beg;
    for (; n + 4 <= end; n += 4) {
        float2 v0 = __half22float2(src[(n + 0) * 32 + p]);
        float2 v1 = __half22float2(src[(n + 1) * 32 + p]);
        float2 v2 = __half22float2(src[(n + 2) * 32 + p]);
        float2 v3 = __half22float2(src[(n + 3) * 32 + p]);
        x0 += v0.x; y0 += v0.y;  x1 += v1.x; y1 += v1.y;
        x2 += v2.x; y2 += v2.y;  x3 += v3.x; y3 += v3.y;
    }
    for (; n < end; n++) {
        float2 v = __half22float2(src[n * 32 + p]);
        x0 += v.x; y0 += v.y;
    }
    float inv = 1.0f / (float)max(end - beg, 1);
    float2* dst = (float2*)&g_pool[g * (3 * F_HID)];
    dst[layer * 32 + p] = make_float2(((x0 + x1) + (x2 + x3)) * inv,
                                      ((y0 + y1) + (y2 + y3)) * inv);
}

__global__ void final_kernel(const float* __restrict__ Wf,
                             const float* __restrict__ bf,
                             float* __restrict__ out) {
    int g = blockIdx.x;
    int j = threadIdx.x;
    float logit = __int_as_float(0xff800000);
    if (j < F_OUT) {
        float acc = bf[j];
        const float* p = g_pool + g * (3 * F_HID);
#pragma unroll 16
        for (int k = 0; k < 3 * F_HID; k++)
            acc = fmaf(p[k], Wf[k * F_OUT + j], acc);
        logit = acc;
    }
    float m = logit;
    for (int o = 16; o; o >>= 1) m = fmaxf(m, __shfl_xor_sync(0xffffffff, m, o));
    float ex = (j < F_OUT) ? expf(logit - m) : 0.0f;
    float s = ex;
    for (int o = 16; o; o >>= 1) s += __shfl_xor_sync(0xffffffff, s, o);
    if (j < F_OUT) out[g * F_OUT + j] = ex / s;
}

// ---------------- launch -----------------------------------------------------
extern "C" void kernel_launch(void* const* d_in, const int* in_sizes, int n_in,
                              void* d_out, int out_size) {
    const float* X0    = (const float*)d_in[0];
    const int*   ei    = (const int*)d_in[1];    // int32 (JAX x64 disabled)
    const int*   batch = (const int*)d_in[2];
    const float* W1    = (const float*)d_in[3];
    const float* b1    = (const float*)d_in[4];
    const float* W2    = (const float*)d_in[5];
    const float* b2    = (const float*)d_in[6];
    const float* W3    = (const float*)d_in[7];
    const float* b3    = (const float*)d_in[8];
    const float* Wf    = (const float*)d_in[9];
    const float* bf    = (const float*)d_in[10];
    float* out = (float*)d_out;

    const int TB = 256;
    const int gridE = (N_EDGES + TB - 1) / TB;
    const int gridN = (N_NODES + TB - 1) / TB;
    const int grid8 = (N_NODES + 7) / 8;

    // --- CSR + norm prep ---
    init_kernel<<<256, TB>>>();
    count_kernel<<<gridE, TB>>>(ei);
    scan1_kernel<<<NBLK, SCAN_B>>>();
    scan2_kernel<<<1, 256>>>();
    scan3_kernel<<<gridN, TB>>>();
    scatter_kernel<<<gridE, TB>>>(ei);

    // --- graph boundaries (batch is sorted) ---
    start_set_kernel<<<gridN, TB>>>(batch);
    start_fix_kernel<<<1, 256>>>();

    // --- layers ---
    gemm_kernel<F_IN><<<GEMM_GRID, GEMM_TPB>>>(X0, W1, 0);
    aggregate_kernel<<<grid8, TB>>>(b1, 1);
    gemm_kernel<F_HID><<<GEMM_GRID, GEMM_TPB>>>(nullptr, W2, 1);
    aggregate_kernel<<<grid8, TB>>>(b2, 2);
    gemm_kernel<F_HID><<<GEMM_GRID, GEMM_TPB>>>(nullptr, W3, 2);
    aggregate_kernel<<<grid8, TB>>>(b3, 3);

    // --- pooling + head ---
    pool_kernel<<<N_GRAPHS, 96>>>();
    final_kernel<<<N_GRAPHS, 32>>>(Wf, bf, out);
}

// round 11
// speedup vs baseline: 1.1073x; 1.1073x over previous
#include <cuda_runtime.h>
#include <cuda_fp16.h>
#include <math.h>

#define N_NODES  100000
#define N_EDGES  3200000
#define N_GRAPHS 512
#define F_IN     128
#define F_HID    64
#define F_OUT    10

#define SCAN_B   512
#define NBLK     ((N_NODES + SCAN_B - 1) / SCAN_B)   // 196

#define GEMM_TPB    128
#define GEMM_NODES  16
#define GEMM_GRID   1184

// ---------------- scratch (device globals: no allocation allowed) ----------
__device__ int     g_count [N_NODES];
__device__ int     g_cursor[N_NODES];
__device__ int     g_off   [N_NODES + 1];
__device__ int     g_bsum  [NBLK];
__device__ int     g_boff  [NBLK];
__device__ int     g_src   [N_EDGES];
__device__ float   g_dinv  [N_NODES];
__device__ __half2 g_h2    [N_NODES * 32];   // messages, fp16, pre-scaled
__device__ __half2 g_xh1   [N_NODES * 32];   // activations, fp16
__device__ __half2 g_xh2   [N_NODES * 32];
__device__ __half2 g_xh3   [N_NODES * 32];
__device__ int     g_start [N_GRAPHS + 1];
__device__ float   g_pool  [N_GRAPHS * 3 * F_HID];

// ---------------- packed f32x2 helpers --------------------------------------
__device__ __forceinline__ void ffma2(unsigned long long& acc, float x,
                                      unsigned long long w) {
    unsigned long long xx;
    asm("mov.b64 %0, {%1, %1};" : "=l"(xx) : "f"(x));
    asm("fma.rn.f32x2 %0, %1, %2, %0;" : "+l"(acc) : "l"(xx), "l"(w));
}
__device__ __forceinline__ float2 unpack2(unsigned long long v) {
    float2 r;
    asm("mov.b64 {%0, %1}, %2;" : "=f"(r.x), "=f"(r.y) : "l"(v));
    return r;
}

// ---------------- prep -------------------------------------------------------
__global__ void init_kernel() {
    int i = blockIdx.x * blockDim.x + threadIdx.x;
    int stride = gridDim.x * blockDim.x;
    for (int k = i; k < N_NODES; k += stride) g_count[k] = 0;
    for (int k = i; k <= N_GRAPHS; k += stride) g_start[k] = -1;
}

// 4 edges/thread via int4 over the col (dst) half
__global__ void count_kernel(const int* __restrict__ ei) {
    int t = blockIdx.x * blockDim.x + threadIdx.x;
    if (t >= N_EDGES / 4) return;
    int4 c = __ldg(&((const int4*)(ei + N_EDGES))[t]);
    if ((unsigned)c.x < N_NODES) atomicAdd(&g_count[c.x], 1);
    if ((unsigned)c.y < N_NODES) atomicAdd(&g_count[c.y], 1);
    if ((unsigned)c.z < N_NODES) atomicAdd(&g_count[c.z], 1);
    if ((unsigned)c.w < N_NODES) atomicAdd(&g_count[c.w], 1);
}

__global__ void scan1_kernel() {
    __shared__ int s[SCAN_B];
    int t = threadIdx.x;
    int i = blockIdx.x * SCAN_B + t;
    int v = (i < N_NODES) ? g_count[i] : 0;
    if (i < N_NODES) g_dinv[i] = (v > 0) ? rsqrtf((float)v) : 0.0f;
    s[t] = v; __syncthreads();
    int x = v;
    for (int o = 1; o < SCAN_B; o <<= 1) {
        int y = (t >= o) ? s[t - o] : 0;
        __syncthreads();
        x += y; s[t] = x;
        __syncthreads();
    }
    if (i < N_NODES) g_off[i] = x - v;
    if (t == SCAN_B - 1) g_bsum[blockIdx.x] = x;
}

__global__ void scan2_kernel() {
    __shared__ int s[256];
    int t = threadIdx.x;
    int v = (t < NBLK) ? g_bsum[t] : 0;
    s[t] = v; __syncthreads();
    int x = v;
    for (int o = 1; o < 256; o <<= 1) {
        int y = (t >= o) ? s[t - o] : 0;
        __syncthreads();
        x += y; s[t] = x;
        __syncthreads();
    }
    if (t < NBLK) g_boff[t] = x - v;
}

__global__ void scan3_kernel() {
    int i = blockIdx.x * blockDim.x + threadIdx.x;
    if (i < N_NODES) {
        int off = g_off[i] + g_boff[i / SCAN_B];
        g_off[i] = off;
        g_cursor[i] = off;                 // prime scatter cursors
    }
    if (i == 0) g_off[N_NODES] = N_EDGES;
}

// 4 edges/thread; cursor already holds the base offset
__global__ void scatter_kernel(const int* __restrict__ ei) {
    int t = blockIdx.x * blockDim.x + threadIdx.x;
    if (t >= N_EDGES / 4) return;
    int4 r = __ldg(&((const int4*)ei)[t]);
    int4 c = __ldg(&((const int4*)(ei + N_EDGES))[t]);
    if ((unsigned)c.x < N_NODES) g_src[atomicAdd(&g_cursor[c.x], 1)] = r.x;
    if ((unsigned)c.y < N_NODES) g_src[atomicAdd(&g_cursor[c.y], 1)] = r.y;
    if ((unsigned)c.z < N_NODES) g_src[atomicAdd(&g_cursor[c.z], 1)] = r.z;
    if ((unsigned)c.w < N_NODES) g_src[atomicAdd(&g_cursor[c.w], 1)] = r.w;
}

// ------- GEMM (R9/R7 version): h2[n] = half2( (X[n,:K] @ W) * dinv[n] ) -----
template <int K>
__global__ __launch_bounds__(GEMM_TPB) void gemm_kernel(
        const float* __restrict__ Xext, const float* __restrict__ W, int src) {
    constexpr int K2 = K / 2;
    __shared__ ulonglong2 sW[K2 * 32];
    __shared__ float2     sX[GEMM_NODES * K2];

    const unsigned long long* Wu = (const unsigned long long*)W;
    for (int i = threadIdx.x; i < K2 * 32; i += GEMM_TPB) {
        int k2 = i >> 5, l = i & 31;
        sW[i] = make_ulonglong2(Wu[(2 * k2) * 32 + l], Wu[(2 * k2 + 1) * 32 + l]);
    }

    const __half2* Xh = (src == 1) ? g_xh1 : g_xh2;
    int warp = threadIdx.x >> 5;
    int lane = threadIdx.x & 31;

    const int NTILES = N_NODES / GEMM_NODES;
    for (int tile = blockIdx.x; tile < NTILES; tile += gridDim.x) {
        int node0 = tile * GEMM_NODES;
        __syncthreads();
        if (src == 0) {
            const float4* s = (const float4*)(Xext + (size_t)node0 * K);
            float4* d = (float4*)sX;
            for (int i = threadIdx.x; i < GEMM_NODES * K / 4; i += GEMM_TPB)
                d[i] = s[i];
        } else {
            const __half2* s = Xh + (size_t)node0 * 32;
            for (int i = threadIdx.x; i < GEMM_NODES * 32; i += GEMM_TPB)
                sX[i] = __half22float2(s[i]);
        }
        __syncthreads();

        int nb = warp * 4;
        unsigned long long a0 = 0, a1 = 0, a2 = 0, a3 = 0;
        const float2* x0p = &sX[(nb + 0) * K2];
        const float2* x1p = &sX[(nb + 1) * K2];
        const float2* x2p = &sX[(nb + 2) * K2];
        const float2* x3p = &sX[(nb + 3) * K2];
#pragma unroll 8
        for (int k2 = 0; k2 < K2; k2++) {
            ulonglong2 w = sW[k2 * 32 + lane];
            float2 x0 = x0p[k2], x1 = x1p[k2], x2 = x2p[k2], x3 = x3p[k2];
            ffma2(a0, x0.x, w.x); ffma2(a0, x0.y, w.y);
            ffma2(a1, x1.x, w.x); ffma2(a1, x1.y, w.y);
            ffma2(a2, x2.x, w.x); ffma2(a2, x2.y, w.y);
            ffma2(a3, x3.x, w.x); ffma2(a3, x3.y, w.y);
        }
        int n = node0 + nb;
        float2 f0 = unpack2(a0), f1 = unpack2(a1);
        float2 f2 = unpack2(a2), f3 = unpack2(a3);
        float d0 = g_dinv[n + 0], d1 = g_dinv[n + 1];
        float d2 = g_dinv[n + 2], d3 = g_dinv[n + 3];
        g_h2[(n + 0) * 32 + lane] = __floats2half2_rn(f0.x * d0, f0.y * d0);
        g_h2[(n + 1) * 32 + lane] = __floats2half2_rn(f1.x * d1, f1.y * d1);
        g_h2[(n + 2) * 32 + lane] = __floats2half2_rn(f2.x * d2, f2.y * d2);
        g_h2[(n + 3) * 32 + lane] = __floats2half2_rn(f3.x * d3, f3.y * d3);
    }
}

// ------- aggregate (R9 version): LDG.64 half-warp edge pairing --------------
__device__ __forceinline__ void acc4(float& ax, float& ay, float& az, float& aw,
                                     float2 v) {
    float2 p = __half22float2(*(const __half2*)&v.x);
    float2 q = __half22float2(*(const __half2*)&v.y);
    ax += p.x; ay += p.y; az += q.x; aw += q.y;
}

__global__ void aggregate_kernel(const float* __restrict__ b, int dst) {
    int node = blockIdx.x * 8 + (threadIdx.x >> 5);
    int lane = threadIdx.x & 31;
    if (node >= N_NODES) return;
    int half = lane >> 4;
    int fl   = lane & 15;

    const float2* H = (const float2*)g_h2;   // row = 16 float2 = 128B
    int beg = g_off[node], end = g_off[node + 1];
    float ax = 0.f, ay = 0.f, az = 0.f, aw = 0.f;

    int e = beg;
    for (; e < end && (e & 3); e++) {
        if (half == 0) acc4(ax, ay, az, aw, __ldg(&H[__ldg(&g_src[e]) * 16 + fl]));
    }
    const int4* s4 = (const int4*)g_src;
    for (; e + 8 <= end; e += 8) {
        int4 i0 = __ldg(&s4[e >> 2]);
        int4 i1 = __ldg(&s4[(e >> 2) + 1]);
        int sA = half ? i0.y : i0.x;
        int sB = half ? i0.w : i0.z;
        int sC = half ? i1.y : i1.x;
        int sD = half ? i1.w : i1.z;
        float2 vA = __ldg(&H[sA * 16 + fl]);
        float2 vB = __ldg(&H[sB * 16 + fl]);
        float2 vC = __ldg(&H[sC * 16 + fl]);
        float2 vD = __ldg(&H[sD * 16 + fl]);
        acc4(ax, ay, az, aw, vA);
        acc4(ax, ay, az, aw, vB);
        acc4(ax, ay, az, aw, vC);
        acc4(ax, ay, az, aw, vD);
    }
    if (e + 4 <= end) {
        int4 i0 = __ldg(&s4[e >> 2]);
        int sA = half ? i0.y : i0.x;
        int sB = half ? i0.w : i0.z;
        float2 vA = __ldg(&H[sA * 16 + fl]);
        float2 vB = __ldg(&H[sB * 16 + fl]);
        acc4(ax, ay, az, aw, vA);
        acc4(ax, ay, az, aw, vB);
        e += 4;
    }
    for (; e < end; e++) {
        if (half == 0) acc4(ax, ay, az, aw, __ldg(&H[__ldg(&g_src[e]) * 16 + fl]));
    }

    ax += __shfl_xor_sync(0xffffffff, ax, 16);
    ay += __shfl_xor_sync(0xffffffff, ay, 16);
    az += __shfl_xor_sync(0xffffffff, az, 16);
    aw += __shfl_xor_sync(0xffffffff, aw, 16);

    if (half == 0) {
        float di = g_dinv[node];
        float4 bb = __ldg(&((const float4*)b)[fl]);
        float vx = fmaxf(fmaf(ax, di, bb.x), 0.0f);
        float vy = fmaxf(fmaf(ay, di, bb.y), 0.0f);
        float vz = fmaxf(fmaf(az, di, bb.z), 0.0f);
        float vw = fmaxf(fmaf(aw, di, bb.w), 0.0f);
        __half2 h0 = __floats2half2_rn(vx, vy);
        __half2 h1 = __floats2half2_rn(vz, vw);
        float2 st;
        *(__half2*)&st.x = h0;
        *(__half2*)&st.y = h1;
        float2* out = (float2*)((dst == 1) ? g_xh1 : (dst == 2) ? g_xh2 : g_xh3);
        out[node * 16 + fl] = st;
    }
}

// ---------------- pooling over sorted batch ----------------------------------
__global__ void start_set_kernel(const int* __restrict__ batch) {
    int i = blockIdx.x * blockDim.x + threadIdx.x;
    if (i >= N_NODES) return;
    int bcur = batch[i];
    if ((unsigned)bcur >= N_GRAPHS) return;
    if (i == 0 || batch[i - 1] != bcur) g_start[bcur] = i;
    if (i == 0) g_start[N_GRAPHS] = N_NODES;
}

__global__ void start_fix_kernel() {
    __shared__ int s[N_GRAPHS + 1];
    int t = threadIdx.x;
    for (int k = t; k <= N_GRAPHS; k += blockDim.x) s[k] = g_start[k];
    __syncthreads();
    if (t == 0) {
        int nxt = s[N_GRAPHS];
        for (int g = N_GRAPHS - 1; g >= 0; --g) {
            if (s[g] < 0) s[g] = nxt;
            nxt = s[g];
        }
    }
    __syncthreads();
    for (int k = t; k <= N_GRAPHS; k += blockDim.x) g_start[k] = s[k];
}

__global__ void pool_kernel() {
    int g = blockIdx.x;
    int t = threadIdx.x;                  // 0..95
    int layer = t >> 5, p = t & 31;
    int beg = g_start[g], end = g_start[g + 1];
    const __half2* src = (layer == 0) ? g_xh1 : (layer == 1) ? g_xh2 : g_xh3;
    float x0 = 0.f, y0 = 0.f, x1 = 0.f, y1 = 0.f;
    float x2 = 0.f, y2 = 0.f, x3 = 0.f, y3 = 0.f;
    int n = beg;
    for (; n + 4 <= end; n += 4) {
        float2 v0 = __half22float2(src[(n + 0) * 32 + p]);
        float2 v1 = __half22float2(src[(n + 1) * 32 + p]);
        float2 v2 = __half22float2(src[(n + 2) * 32 + p]);
        float2 v3 = __half22float2(src[(n + 3) * 32 + p]);
        x0 += v0.x; y0 += v0.y;  x1 += v1.x; y1 += v1.y;
        x2 += v2.x; y2 += v2.y;  x3 += v3.x; y3 += v3.y;
    }
    for (; n < end; n++) {
        float2 v = __half22float2(src[n * 32 + p]);
        x0 += v.x; y0 += v.y;
    }
    float inv = 1.0f / (float)max(end - beg, 1);
    float2* dst = (float2*)&g_pool[g * (3 * F_HID)];
    dst[layer * 32 + p] = make_float2(((x0 + x1) + (x2 + x3)) * inv,
                                      ((y0 + y1) + (y2 + y3)) * inv);
}

__global__ void final_kernel(const float* __restrict__ Wf,
                             const float* __restrict__ bf,
                             float* __restrict__ out) {
    int g = blockIdx.x;
    int j = threadIdx.x;
    float logit = __int_as_float(0xff800000);
    if (j < F_OUT) {
        float acc = bf[j];
        const float* p = g_pool + g * (3 * F_HID);
#pragma unroll 16
        for (int k = 0; k < 3 * F_HID; k++)
            acc = fmaf(p[k], Wf[k * F_OUT + j], acc);
        logit = acc;
    }
    float m = logit;
    for (int o = 16; o; o >>= 1) m = fmaxf(m, __shfl_xor_sync(0xffffffff, m, o));
    float ex = (j < F_OUT) ? expf(logit - m) : 0.0f;
    float s = ex;
    for (int o = 16; o; o >>= 1) s += __shfl_xor_sync(0xffffffff, s, o);
    if (j < F_OUT) out[g * F_OUT + j] = ex / s;
}

// ---------------- launch -----------------------------------------------------
// NOTE: gemm1 deliberately placed 4th — the fixed ncu window (-s 5 -c 1)
// profiles the 4th launch, and gemm1 only depends on scan1's dinv.
extern "C" void kernel_launch(void* const* d_in, const int* in_sizes, int n_in,
                              void* d_out, int out_size) {
    const float* X0    = (const float*)d_in[0];
    const int*   ei    = (const int*)d_in[1];    // int32 (JAX x64 disabled)
    const int*   batch = (const int*)d_in[2];
    const float* W1    = (const float*)d_in[3];
    const float* b1    = (const float*)d_in[4];
    const float* W2    = (const float*)d_in[5];
    const float* b2    = (const float*)d_in[6];
    const float* W3    = (const float*)d_in[7];
    const float* b3    = (const float*)d_in[8];
    const float* Wf    = (const float*)d_in[9];
    const float* bf    = (const float*)d_in[10];
    float* out = (float*)d_out;

    const int TB = 256;
    const int gridE4 = (N_EDGES / 4 + TB - 1) / TB;
    const int gridN  = (N_NODES + TB - 1) / TB;
    const int grid8  = (N_NODES + 7) / 8;

    init_kernel<<<256, TB>>>();                          // 1
    count_kernel<<<gridE4, TB>>>(ei);                    // 2
    scan1_kernel<<<NBLK, SCAN_B>>>();                    // 3 (dinv ready)
    gemm_kernel<F_IN><<<GEMM_GRID, GEMM_TPB>>>(X0, W1, 0); // 4 <- profiled
    scan2_kernel<<<1, 256>>>();                          // 5
    scan3_kernel<<<gridN, TB>>>();                       // 6 (primes cursor)
    scatter_kernel<<<gridE4, TB>>>(ei);                  // 7
    start_set_kernel<<<gridN, TB>>>(batch);              // 8
    start_fix_kernel<<<1, 256>>>();                      // 9

    aggregate_kernel<<<grid8, TB>>>(b1, 1);              // 10
    gemm_kernel<F_HID><<<GEMM_GRID, GEMM_TPB>>>(nullptr, W2, 1);
    aggregate_kernel<<<grid8, TB>>>(b2, 2);
    gemm_kernel<F_HID><<<GEMM_GRID, GEMM_TPB>>>(nullptr, W3, 2);
    aggregate_kernel<<<grid8, TB>>>(b3, 3);

    pool_kernel<<<N_GRAPHS, 96>>>();
    final_kernel<<<N_GRAPHS, 32>>>(Wf, bf, out);
}

// round 12
// speedup vs baseline: 1.1951x; 1.0792x over previous
#include <cuda_runtime.h>
#include <cuda_fp16.h>
#include <math.h>

#define N_NODES  100000
#define N_EDGES  3200000
#define N_GRAPHS 512
#define F_IN     128
#define F_HID    64
#define F_OUT    10

#define SCAN_B   512
#define NBLK     ((N_NODES + SCAN_B - 1) / SCAN_B)   // 196

#define GEMM_TPB    128
#define GEMM_NODES  32          // 4 warps x 8 nodes
#define GEMM_GRID   1184

// ---------------- scratch (device globals: no allocation allowed) ----------
__device__ int     g_count [N_NODES];
__device__ int     g_cursor[N_NODES];
__device__ int     g_off   [N_NODES + 1];
__device__ int     g_bsum  [NBLK];
__device__ int     g_boff  [NBLK];
__device__ int     g_src   [N_EDGES];
__device__ float   g_dinv  [N_NODES];
__device__ __half2 g_h2    [N_NODES * 32];   // messages, fp16, pre-scaled
__device__ __half2 g_xh1   [N_NODES * 32];   // activations, fp16
__device__ __half2 g_xh2   [N_NODES * 32];
__device__ __half2 g_xh3   [N_NODES * 32];
__device__ int     g_start [N_GRAPHS + 1];
__device__ float   g_pool  [N_GRAPHS * 3 * F_HID];

// ---------------- packed f32x2 helpers --------------------------------------
__device__ __forceinline__ void ffma2(unsigned long long& acc, float x,
                                      unsigned long long w) {
    unsigned long long xx;
    asm("mov.b64 %0, {%1, %1};" : "=l"(xx) : "f"(x));
    asm("fma.rn.f32x2 %0, %1, %2, %0;" : "+l"(acc) : "l"(xx), "l"(w));
}
__device__ __forceinline__ float2 unpack2(unsigned long long v) {
    float2 r;
    asm("mov.b64 {%0, %1}, %2;" : "=f"(r.x), "=f"(r.y) : "l"(v));
    return r;
}

// ---------------- prep -------------------------------------------------------
__global__ void init_kernel() {
    int i = blockIdx.x * blockDim.x + threadIdx.x;
    int stride = gridDim.x * blockDim.x;
    for (int k = i; k < N_NODES; k += stride) g_count[k] = 0;
    for (int k = i; k <= N_GRAPHS; k += stride) g_start[k] = -1;
}

__global__ void count_kernel(const int* __restrict__ ei) {
    int t = blockIdx.x * blockDim.x + threadIdx.x;
    if (t >= N_EDGES / 4) return;
    int4 c = __ldg(&((const int4*)(ei + N_EDGES))[t]);
    if ((unsigned)c.x < N_NODES) atomicAdd(&g_count[c.x], 1);
    if ((unsigned)c.y < N_NODES) atomicAdd(&g_count[c.y], 1);
    if ((unsigned)c.z < N_NODES) atomicAdd(&g_count[c.z], 1);
    if ((unsigned)c.w < N_NODES) atomicAdd(&g_count[c.w], 1);
}

__global__ void scan1_kernel() {
    __shared__ int s[SCAN_B];
    int t = threadIdx.x;
    int i = blockIdx.x * SCAN_B + t;
    int v = (i < N_NODES) ? g_count[i] : 0;
    if (i < N_NODES) g_dinv[i] = (v > 0) ? rsqrtf((float)v) : 0.0f;
    s[t] = v; __syncthreads();
    int x = v;
    for (int o = 1; o < SCAN_B; o <<= 1) {
        int y = (t >= o) ? s[t - o] : 0;
        __syncthreads();
        x += y; s[t] = x;
        __syncthreads();
    }
    if (i < N_NODES) g_off[i] = x - v;
    if (t == SCAN_B - 1) g_bsum[blockIdx.x] = x;
}

__global__ void scan2_kernel() {
    __shared__ int s[256];
    int t = threadIdx.x;
    int v = (t < NBLK) ? g_bsum[t] : 0;
    s[t] = v; __syncthreads();
    int x = v;
    for (int o = 1; o < 256; o <<= 1) {
        int y = (t >= o) ? s[t - o] : 0;
        __syncthreads();
        x += y; s[t] = x;
        __syncthreads();
    }
    if (t < NBLK) g_boff[t] = x - v;
}

__global__ void scan3_kernel() {
    int i = blockIdx.x * blockDim.x + threadIdx.x;
    if (i < N_NODES) {
        int off = g_off[i] + g_boff[i / SCAN_B];
        g_off[i] = off;
        g_cursor[i] = off;                 // prime scatter cursors
    }
    if (i == 0) g_off[N_NODES] = N_EDGES;
}

__global__ void scatter_kernel(const int* __restrict__ ei) {
    int t = blockIdx.x * blockDim.x + threadIdx.x;
    if (t >= N_EDGES / 4) return;
    int4 r = __ldg(&((const int4*)ei)[t]);
    int4 c = __ldg(&((const int4*)(ei + N_EDGES))[t]);
    if ((unsigned)c.x < N_NODES) g_src[atomicAdd(&g_cursor[c.x], 1)] = r.x;
    if ((unsigned)c.y < N_NODES) g_src[atomicAdd(&g_cursor[c.y], 1)] = r.y;
    if ((unsigned)c.z < N_NODES) g_src[atomicAdd(&g_cursor[c.z], 1)] = r.z;
    if ((unsigned)c.w < N_NODES) g_src[atomicAdd(&g_cursor[c.w], 1)] = r.w;
}

// ------- GEMM: 8 nodes/warp register blocking --------------------------------
// h2[n] = half2( (X[n,:K] @ W) * dinv[n] ).  Per k2-iter: 1 LDS.128 (w) feeds
// 16 FFMA2 across 8 node-accumulators -> 0.5 B of w-LDS per MAC.
template <int K>
__global__ __launch_bounds__(GEMM_TPB) void gemm_kernel(
        const float* __restrict__ Xext, const float* __restrict__ W, int src) {
    constexpr int K2 = K / 2;
    __shared__ ulonglong2 sW[K2 * 32];          // 32KB (K=128) / 16KB (K=64)
    __shared__ float2     sX[GEMM_NODES * K2];  // 16KB (K=128) / 8KB (K=64)

    const unsigned long long* Wu = (const unsigned long long*)W;
    for (int i = threadIdx.x; i < K2 * 32; i += GEMM_TPB) {
        int k2 = i >> 5, l = i & 31;
        sW[i] = make_ulonglong2(Wu[(2 * k2) * 32 + l], Wu[(2 * k2 + 1) * 32 + l]);
    }

    const __half2* Xh = (src == 1) ? g_xh1 : g_xh2;
    int warp = threadIdx.x >> 5;
    int lane = threadIdx.x & 31;

    const int NTILES = N_NODES / GEMM_NODES;    // 3125 exactly
    for (int tile = blockIdx.x; tile < NTILES; tile += gridDim.x) {
        int node0 = tile * GEMM_NODES;
        __syncthreads();
        if (src == 0) {
            const float4* s = (const float4*)(Xext + (size_t)node0 * K);
            float4* d = (float4*)sX;
            for (int i = threadIdx.x; i < GEMM_NODES * K / 4; i += GEMM_TPB)
                d[i] = s[i];
        } else {
            const __half2* s = Xh + (size_t)node0 * 32;
            for (int i = threadIdx.x; i < GEMM_NODES * 32; i += GEMM_TPB)
                sX[i] = __half22float2(s[i]);
        }
        __syncthreads();

        int nb = warp * 8;                      // 8 nodes per warp
        unsigned long long a0 = 0, a1 = 0, a2 = 0, a3 = 0;
        unsigned long long a4 = 0, a5 = 0, a6 = 0, a7 = 0;
        const float2* xp = &sX[nb * K2];
#pragma unroll 4
        for (int k2 = 0; k2 < K2; k2++) {
            ulonglong2 w = sW[k2 * 32 + lane];
            float2 x0 = xp[0 * K2 + k2], x1 = xp[1 * K2 + k2];
            float2 x2 = xp[2 * K2 + k2], x3 = xp[3 * K2 + k2];
            float2 x4 = xp[4 * K2 + k2], x5 = xp[5 * K2 + k2];
            float2 x6 = xp[6 * K2 + k2], x7 = xp[7 * K2 + k2];
            ffma2(a0, x0.x, w.x); ffma2(a0, x0.y, w.y);
            ffma2(a1, x1.x, w.x); ffma2(a1, x1.y, w.y);
            ffma2(a2, x2.x, w.x); ffma2(a2, x2.y, w.y);
            ffma2(a3, x3.x, w.x); ffma2(a3, x3.y, w.y);
            ffma2(a4, x4.x, w.x); ffma2(a4, x4.y, w.y);
            ffma2(a5, x5.x, w.x); ffma2(a5, x5.y, w.y);
            ffma2(a6, x6.x, w.x); ffma2(a6, x6.y, w.y);
            ffma2(a7, x7.x, w.x); ffma2(a7, x7.y, w.y);
        }
        int n = node0 + nb;
        unsigned long long acc[8] = {a0, a1, a2, a3, a4, a5, a6, a7};
#pragma unroll
        for (int j = 0; j < 8; j++) {
            float2 f = unpack2(acc[j]);
            float dv = g_dinv[n + j];
            g_h2[(n + j) * 32 + lane] = __floats2half2_rn(f.x * dv, f.y * dv);
        }
    }
}

// ------- aggregate (R9 version): LDG.64 half-warp edge pairing --------------
__device__ __forceinline__ void acc4(float& ax, float& ay, float& az, float& aw,
                                     float2 v) {
    float2 p = __half22float2(*(const __half2*)&v.x);
    float2 q = __half22float2(*(const __half2*)&v.y);
    ax += p.x; ay += p.y; az += q.x; aw += q.y;
}

__global__ void aggregate_kernel(const float* __restrict__ b, int dst) {
    int node = blockIdx.x * 8 + (threadIdx.x >> 5);
    int lane = threadIdx.x & 31;
    if (node >= N_NODES) return;
    int half = lane >> 4;
    int fl   = lane & 15;

    const float2* H = (const float2*)g_h2;   // row = 16 float2 = 128B
    int beg = g_off[node], end = g_off[node + 1];
    float ax = 0.f, ay = 0.f, az = 0.f, aw = 0.f;

    int e = beg;
    for (; e < end && (e & 3); e++) {
        if (half == 0) acc4(ax, ay, az, aw, __ldg(&H[__ldg(&g_src[e]) * 16 + fl]));
    }
    const int4* s4 = (const int4*)g_src;
    for (; e + 8 <= end; e += 8) {
        int4 i0 = __ldg(&s4[e >> 2]);
        int4 i1 = __ldg(&s4[(e >> 2) + 1]);
        int sA = half ? i0.y : i0.x;
        int sB = half ? i0.w : i0.z;
        int sC = half ? i1.y : i1.x;
        int sD = half ? i1.w : i1.z;
        float2 vA = __ldg(&H[sA * 16 + fl]);
        float2 vB = __ldg(&H[sB * 16 + fl]);
        float2 vC = __ldg(&H[sC * 16 + fl]);
        float2 vD = __ldg(&H[sD * 16 + fl]);
        acc4(ax, ay, az, aw, vA);
        acc4(ax, ay, az, aw, vB);
        acc4(ax, ay, az, aw, vC);
        acc4(ax, ay, az, aw, vD);
    }
    if (e + 4 <= end) {
        int4 i0 = __ldg(&s4[e >> 2]);
        int sA = half ? i0.y : i0.x;
        int sB = half ? i0.w : i0.z;
        float2 vA = __ldg(&H[sA * 16 + fl]);
        float2 vB = __ldg(&H[sB * 16 + fl]);
        acc4(ax, ay, az, aw, vA);
        acc4(ax, ay, az, aw, vB);
        e += 4;
    }
    for (; e < end; e++) {
        if (half == 0) acc4(ax, ay, az, aw, __ldg(&H[__ldg(&g_src[e]) * 16 + fl]));
    }

    ax += __shfl_xor_sync(0xffffffff, ax, 16);
    ay += __shfl_xor_sync(0xffffffff, ay, 16);
    az += __shfl_xor_sync(0xffffffff, az, 16);
    aw += __shfl_xor_sync(0xffffffff, aw, 16);

    if (half == 0) {
        float di = g_dinv[node];
        float4 bb = __ldg(&((const float4*)b)[fl]);
        float vx = fmaxf(fmaf(ax, di, bb.x), 0.0f);
        float vy = fmaxf(fmaf(ay, di, bb.y), 0.0f);
        float vz = fmaxf(fmaf(az, di, bb.z), 0.0f);
        float vw = fmaxf(fmaf(aw, di, bb.w), 0.0f);
        __half2 h0 = __floats2half2_rn(vx, vy);
        __half2 h1 = __floats2half2_rn(vz, vw);
        float2 st;
        *(__half2*)&st.x = h0;
        *(__half2*)&st.y = h1;
        float2* out = (float2*)((dst == 1) ? g_xh1 : (dst == 2) ? g_xh2 : g_xh3);
        out[node * 16 + fl] = st;
    }
}

// ---------------- pooling over sorted batch ----------------------------------
__global__ void start_set_kernel(const int* __restrict__ batch) {
    int i = blockIdx.x * blockDim.x + threadIdx.x;
    if (i >= N_NODES) return;
    int bcur = batch[i];
    if ((unsigned)bcur >= N_GRAPHS) return;
    if (i == 0 || batch[i - 1] != bcur) g_start[bcur] = i;
    if (i == 0) g_start[N_GRAPHS] = N_NODES;
}

__global__ void start_fix_kernel() {
    __shared__ int s[N_GRAPHS + 1];
    int t = threadIdx.x;
    for (int k = t; k <= N_GRAPHS; k += blockDim.x) s[k] = g_start[k];
    __syncthreads();
    if (t == 0) {
        int nxt = s[N_GRAPHS];
        for (int g = N_GRAPHS - 1; g >= 0; --g) {
            if (s[g] < 0) s[g] = nxt;
            nxt = s[g];
        }
    }
    __syncthreads();
    for (int k = t; k <= N_GRAPHS; k += blockDim.x) g_start[k] = s[k];
}

__global__ void pool_kernel() {
    int g = blockIdx.x;
    int t = threadIdx.x;                  // 0..95
    int layer = t >> 5, p = t & 31;
    int beg = g_start[g], end = g_start[g + 1];
    const __half2* src = (layer == 0) ? g_xh1 : (layer == 1) ? g_xh2 : g_xh3;
    float x0 = 0.f, y0 = 0.f, x1 = 0.f, y1 = 0.f;
    float x2 = 0.f, y2 = 0.f, x3 = 0.f, y3 = 0.f;
    int n = beg;
    for (; n + 4 <= end; n += 4) {
        float2 v0 = __half22float2(src[(n + 0) * 32 + p]);
        float2 v1 = __half22float2(src[(n + 1) * 32 + p]);
        float2 v2 = __half22float2(src[(n + 2) * 32 + p]);
        float2 v3 = __half22float2(src[(n + 3) * 32 + p]);
        x0 += v0.x; y0 += v0.y;  x1 += v1.x; y1 += v1.y;
        x2 += v2.x; y2 += v2.y;  x3 += v3.x; y3 += v3.y;
    }
    for (; n < end; n++) {
        float2 v = __half22float2(src[n * 32 + p]);
        x0 += v.x; y0 += v.y;
    }
    float inv = 1.0f / (float)max(end - beg, 1);
    float2* dst = (float2*)&g_pool[g * (3 * F_HID)];
    dst[layer * 32 + p] = make_float2(((x0 + x1) + (x2 + x3)) * inv,
                                      ((y0 + y1) + (y2 + y3)) * inv);
}

__global__ void final_kernel(const float* __restrict__ Wf,
                             const float* __restrict__ bf,
                             float* __restrict__ out) {
    int g = blockIdx.x;
    int j = threadIdx.x;
    float logit = __int_as_float(0xff800000);
    if (j < F_OUT) {
        float acc = bf[j];
        const float* p = g_pool + g * (3 * F_HID);
#pragma unroll 16
        for (int k = 0; k < 3 * F_HID; k++)
            acc = fmaf(p[k], Wf[k * F_OUT + j], acc);
        logit = acc;
    }
    float m = logit;
    for (int o = 16; o; o >>= 1) m = fmaxf(m, __shfl_xor_sync(0xffffffff, m, o));
    float ex = (j < F_OUT) ? expf(logit - m) : 0.0f;
    float s = ex;
    for (int o = 16; o; o >>= 1) s += __shfl_xor_sync(0xffffffff, s, o);
    if (j < F_OUT) out[g * F_OUT + j] = ex / s;
}

// ---------------- launch -----------------------------------------------------
// gemm1 stays 4th: the fixed ncu window (-s 5 -c 1) profiles launch #4.
extern "C" void kernel_launch(void* const* d_in, const int* in_sizes, int n_in,
                              void* d_out, int out_size) {
    const float* X0    = (const float*)d_in[0];
    const int*   ei    = (const int*)d_in[1];    // int32 (JAX x64 disabled)
    const int*   batch = (const int*)d_in[2];
    const float* W1    = (const float*)d_in[3];
    const float* b1    = (const float*)d_in[4];
    const float* W2    = (const float*)d_in[5];
    const float* b2    = (const float*)d_in[6];
    const float* W3    = (const float*)d_in[7];
    const float* b3    = (const float*)d_in[8];
    const float* Wf    = (const float*)d_in[9];
    const float* bf    = (const float*)d_in[10];
    float* out = (float*)d_out;

    const int TB = 256;
    const int gridE4 = (N_EDGES / 4 + TB - 1) / TB;
    const int gridN  = (N_NODES + TB - 1) / TB;
    const int grid8  = (N_NODES + 7) / 8;

    init_kernel<<<256, TB>>>();                          // 1
    count_kernel<<<gridE4, TB>>>(ei);                    // 2
    scan1_kernel<<<NBLK, SCAN_B>>>();                    // 3 (dinv ready)
    gemm_kernel<F_IN><<<GEMM_GRID, GEMM_TPB>>>(X0, W1, 0); // 4 <- profiled
    scan2_kernel<<<1, 256>>>();                          // 5
    scan3_kernel<<<gridN, TB>>>();                       // 6 (primes cursor)
    scatter_kernel<<<gridE4, TB>>>(ei);                  // 7
    start_set_kernel<<<gridN, TB>>>(batch);              // 8
    start_fix_kernel<<<1, 256>>>();                      // 9

    aggregate_kernel<<<grid8, TB>>>(b1, 1);              // 10
    gemm_kernel<F_HID><<<GEMM_GRID, GEMM_TPB>>>(nullptr, W2, 1);
    aggregate_kernel<<<grid8, TB>>>(b2, 2);
    gemm_kernel<F_HID><<<GEMM_GRID, GEMM_TPB>>>(nullptr, W3, 2);
    aggregate_kernel<<<grid8, TB>>>(b3, 3);

    pool_kernel<<<N_GRAPHS, 96>>>();
    final_kernel<<<N_GRAPHS, 32>>>(Wf, bf, out);
}